// round 7
// baseline (speedup 1.0000x reference)
#include <cuda_runtime.h>
#include <cstdint>
#include <math.h>

#define NT     16
#define S_LEN  4096
#define B_SZ   512
#define CHUNK  8
#define NBLK   (B_SZ / 4)

typedef unsigned long long u64;

// Per-row partial results + completion counter (device globals: legal scratch).
__device__ float g_fwd[B_SZ];
__device__ float g_gold[B_SZ];
__device__ unsigned g_done = 0;

// ---- smem address + volatile LDS/STS helpers ----
__device__ __forceinline__ unsigned smem_addr(const void* p) {
    unsigned a;
    asm("{ .reg .u64 t; cvta.to.shared.u64 t, %1; cvt.u32.u64 %0, t; }"
        : "=r"(a) : "l"(p));
    return a;
}
__device__ __forceinline__ void sts32v(unsigned addr, float v) {
    asm volatile("st.volatile.shared.f32 [%0], %1;" :: "r"(addr), "f"(v));
}
// load 16 floats as 8 packed f32x2 (4x 128-bit volatile LDS)
__device__ __forceinline__ void lds_state(unsigned addr, u64* p) {
    asm volatile("ld.volatile.shared.v2.b64 {%0,%1}, [%2];"
                 : "=l"(p[0]), "=l"(p[1]) : "r"(addr));
    asm volatile("ld.volatile.shared.v2.b64 {%0,%1}, [%2];"
                 : "=l"(p[2]), "=l"(p[3]) : "r"(addr + 16));
    asm volatile("ld.volatile.shared.v2.b64 {%0,%1}, [%2];"
                 : "=l"(p[4]), "=l"(p[5]) : "r"(addr + 32));
    asm volatile("ld.volatile.shared.v2.b64 {%0,%1}, [%2];"
                 : "=l"(p[6]), "=l"(p[7]) : "r"(addr + 48));
}

// ---- packed fp32x2 math (Blackwell FFMA2 path) ----
__device__ __forceinline__ u64 mul2(u64 a, u64 b) {
    u64 d; asm("mul.rn.f32x2 %0, %1, %2;" : "=l"(d) : "l"(a), "l"(b)); return d;
}
__device__ __forceinline__ u64 fma2(u64 a, u64 b, u64 c) {
    u64 d; asm("fma.rn.f32x2 %0, %1, %2, %3;" : "=l"(d) : "l"(a), "l"(b), "l"(c)); return d;
}
__device__ __forceinline__ u64 add2(u64 a, u64 b) {
    u64 d; asm("add.rn.f32x2 %0, %1, %2;" : "=l"(d) : "l"(a), "l"(b)); return d;
}
__device__ __forceinline__ u64 pack2(float lo, float hi) {
    u64 d; asm("mov.b64 %0, {%1, %2};" : "=l"(d) : "f"(lo), "f"(hi)); return d;
}
__device__ __forceinline__ void unpack2(u64 v, float& lo, float& hi) {
    asm("mov.b64 {%0, %1}, %2;" : "=f"(lo), "=f"(hi) : "l"(v));
}

// Detect element strides (bytes) of tags/mask buffers (JAX dtype ambiguity).
__device__ __forceinline__ int detect_mask_stride(const unsigned char* mb) {
    return (mb[1] | mb[2] | mb[3]) ? 1 : 4;
}
__device__ __forceinline__ int detect_tag_stride(const void* tp) {
    const int* w = (const int*)tp;
    int nz = 0;
#pragma unroll
    for (int k = 0; k < 32; ++k) nz |= w[1 + 2 * k];   // high halves if int64
    return nz ? 4 : 8;
}

// One forward step for one stream. p[8] = gathered state (packed pairs),
// eT2[8] = packed transition columns. Updates s/ksum, publishes to 'dst'.
__device__ __forceinline__ void fwd_step(const u64* p, const u64* eT2,
                                         float e, int m,
                                         float& s, int& ksum, unsigned dst)
{
    // per-step rescale from state[0]'s exponent (exact 2^-k, off-chain)
    const unsigned ub = (unsigned)p[0];           // low 32 bits = s[0]
    const int ef = (int)((ub >> 23) & 0xffu);
    int   kcur;
    float scale;
    if (ef >= 1 && ef <= 253) {
        kcur  = ef - 127;
        scale = __uint_as_float((unsigned)(254 - ef) << 23);
    } else {
        kcur = 0; scale = 1.0f;
    }

    // 16-term dot as two packed chains of 4
    u64 a = mul2(p[0], eT2[0]);
    a = fma2(p[2], eT2[2], a);
    a = fma2(p[4], eT2[4], a);
    a = fma2(p[6], eT2[6], a);
    u64 b = mul2(p[1], eT2[1]);
    b = fma2(p[3], eT2[3], b);
    b = fma2(p[5], eT2[5], b);
    b = fma2(p[7], eT2[7], b);
    const u64 t2 = add2(a, b);
    float lo, hi;
    unpack2(t2, lo, hi);
    const float acc = lo + hi;

    const float w  = __expf(e) * scale;           // e prefetched: off-chain
    const float ns = acc * w;
    s    = m ? ns : s;
    ksum += m ? kcur : 0;
    sts32v(dst, s);
}

// One block = 64 threads = 2 warps, covering 4 batch rows.
//   warp 0: forward, 2 phase-interleaved streams x 2 rows (16 lanes/row)
//   warp 1: gold path score, loops over the 4 rows (16 lanes/row, 2 at a time)
__global__ void __launch_bounds__(64, 1) crf_fused_kernel(
    const float* __restrict__ emissions,          // [B, S, NT] f32
    const void*  __restrict__ tags_raw,           // [B, S] i32 or i64
    const void*  __restrict__ mask_raw,           // [B, S] u8 or i32 (bool)
    const float* __restrict__ transitions,        // [NT, NT] f32
    const float* __restrict__ start_t,            // [NT] f32
    const float* __restrict__ end_t,              // [NT] f32
    float* __restrict__ out)
{
    const int warp = threadIdx.x >> 5;
    const int lane = threadIdx.x & 31;
    const int j    = lane & 15;                  // tag index
    const int r    = lane >> 4;                  // row-within-stream (0/1)

    const unsigned char* mask_b = (const unsigned char*)mask_raw;
    const unsigned char* tags_b = (const unsigned char*)tags_raw;
    const int mstride = detect_mask_stride(mask_b);

    // state buffers: [stream][parity][rowInStream][tag]  (warp-0 private)
    __shared__ float sbuf[2][2][2][NT];
    __shared__ int   s_last;

    if (warp == 0) {
        // ---------------- forward: 2 streams, rows 4b+{0,1} and 4b+{2,3} ----------
        const int row0 = blockIdx.x * 4 + r;          // stream 0
        const int row1 = row0 + 2;                    // stream 1

        // packed transition column j: eT2[i] = (eT[2i][j], eT[2i+1][j])
        u64 eT2[8];
#pragma unroll
        for (int i = 0; i < 8; ++i)
            eT2[i] = pack2(__expf(transitions[(2 * i) * NT + j]),
                           __expf(transitions[(2 * i + 1) * NT + j]));

        const float* er0 = emissions + (size_t)row0 * S_LEN * NT + j;
        const float* er1 = emissions + (size_t)row1 * S_LEN * NT + j;
        const unsigned char* mr0 = mask_b + (size_t)row0 * S_LEN * mstride;
        const unsigned char* mr1 = mask_b + (size_t)row1 * S_LEN * mstride;

        float s0 = __expf(start_t[j] + er0[0]);
        float s1 = __expf(start_t[j] + er1[0]);
        int   k0 = 0, k1 = 0;

        const unsigned sb = smem_addr(&sbuf[0][0][0][0]);
        // addr(stream st, parity pp, row r) = sb + st*256 + pp*128 + r*64
        const unsigned b0 = sb + (unsigned)(r * 64);          // stream 0 base
        const unsigned b1 = sb + 256u + (unsigned)(r * 64);   // stream 1 base
        unsigned par = 0;                                      // parity byte offset

        sts32v(b0 + (unsigned)(j * 4), s0);       // publish init, parity 0
        sts32v(b1 + (unsigned)(j * 4), s1);

        // prefetch pipelines (per stream)
        float e0[CHUNK], e1[CHUNK];
        int   m0[CHUNK], m1[CHUNK];
#pragma unroll
        for (int p = 0; p < CHUNK; ++p) {
            e0[p] = er0[(size_t)p * NT];  m0[p] = mr0[(size_t)p * mstride];
            e1[p] = er1[(size_t)p * NT];  m1[p] = mr1[(size_t)p * mstride];
        }

        u64 v0[8], v1[8];
        lds_state(b0, v0);                         // prologue load, stream 0

        for (int tb = 0; tb < S_LEN; tb += CHUNK) {
#pragma unroll
            for (int u = 0; u < CHUNK; ++u) {
                const int t = tb + u;
                const int mm0 = (t == 0) ? 0 : m0[u];
                const int mm1 = (t == 0) ? 0 : m1[u];
                const float ee0 = e0[u], ee1 = e1[u];

                const int tp = t + CHUNK;
                if (tp < S_LEN) {
                    e0[u] = er0[(size_t)tp * NT];  m0[u] = mr0[(size_t)tp * mstride];
                    e1[u] = er1[(size_t)tp * NT];  m1[u] = mr1[(size_t)tp * mstride];
                }

                const unsigned npar = par ^ 128u;

                // stream 0: consume v0 (parity par), publish to npar
                fwd_step(v0, eT2, ee0, mm0, s0, k0, b0 + npar + (unsigned)(j * 4));

                // stream 1: load (parity par; written one iteration ago -> drained),
                // consume, publish to npar
                lds_state(b1 + par, v1);
                fwd_step(v1, eT2, ee1, mm1, s1, k1, b1 + npar + (unsigned)(j * 4));

                // stream 0: load next state (STS0 was ~1 tree ago -> drained)
                lds_state(b0 + npar, v0);

                par = npar;
            }
        }

        // forward scores
        const float et = __expf(end_t[j]);
        float r0s = s0 * et, r1s = s1 * et;
#pragma unroll
        for (int off = 8; off >= 1; off >>= 1) {
            r0s += __shfl_xor_sync(0xffffffffu, r0s, off, 16);
            r1s += __shfl_xor_sync(0xffffffffu, r1s, off, 16);
        }
        if (j == 0) {
            g_fwd[row0] = logf(r0s) + (float)k0 * 0.6931471805599453f;
            g_fwd[row1] = logf(r1s) + (float)k1 * 0.6931471805599453f;
        }
    } else {
        // ---------------- gold path score (fp32 exact), 4 rows ----------------
        const int tstride = detect_tag_stride(tags_raw);
#pragma unroll
        for (int r2 = 0; r2 < 2; ++r2) {
            const int row = blockIdx.x * 4 + r2 * 2 + (lane >> 4);
            const unsigned char* trow = tags_b + (size_t)row * S_LEN * tstride;
            const unsigned char* mrow = mask_b + (size_t)row * S_LEN * mstride;
            const float*         erow = emissions + (size_t)row * S_LEN * NT;

            float acc = 0.0f;
            int   cnt = 0;
            for (int t = j; t < S_LEN; t += 16) {
                const int tg = trow[(size_t)t * tstride];
                const int mm = mrow[(size_t)t * mstride];
                cnt += mm ? 1 : 0;
                if (t == 0) {
                    acc += start_t[tg] + erow[tg];
                } else if (mm) {
                    const int tpv = trow[(size_t)(t - 1) * tstride];
                    acc += transitions[tpv * NT + tg] + erow[(size_t)t * NT + tg];
                }
            }
#pragma unroll
            for (int off = 8; off >= 1; off >>= 1) {
                acc += __shfl_xor_sync(0xffffffffu, acc, off, 16);
                cnt += __shfl_xor_sync(0xffffffffu, cnt, off, 16);
            }
            if (j == 0) {
                int last = cnt - 1;
                if (last < 0) last = 0;
                const int lt = trow[(size_t)last * tstride];
                g_gold[row] = acc + end_t[lt];
            }
        }
    }

    // ---------------- last-block reduction ----------------
    __syncthreads();
    if (threadIdx.x == 0) {
        __threadfence();
        const unsigned old = atomicAdd(&g_done, 1u);
        s_last = (old == NBLK - 1u) ? 1 : 0;
    }
    __syncthreads();
    if (s_last) {
        __threadfence();
        float a = 0.0f;
        for (int i = threadIdx.x; i < B_SZ; i += 64)
            a += g_fwd[i] - g_gold[i];
#pragma unroll
        for (int off = 16; off >= 1; off >>= 1)
            a += __shfl_xor_sync(0xffffffffu, a, off);
        __shared__ float wsum[2];
        if ((threadIdx.x & 31) == 0) wsum[threadIdx.x >> 5] = a;
        __syncthreads();
        if (threadIdx.x == 0) {
            out[0] = (wsum[0] + wsum[1]) * (1.0f / (float)B_SZ);
            g_done = 0;                      // reset for next graph replay
        }
    }
}

extern "C" void kernel_launch(void* const* d_in, const int* in_sizes, int n_in,
                              void* d_out, int out_size)
{
    (void)in_sizes; (void)n_in; (void)out_size;
    const float* emissions   = (const float*)d_in[0];
    const void*  tags        = d_in[1];
    const void*  mask        = d_in[2];
    const float* transitions = (const float*)d_in[3];
    const float* start_t     = (const float*)d_in[4];
    const float* end_t       = (const float*)d_in[5];

    crf_fused_kernel<<<NBLK, 64>>>(emissions, tags, mask, transitions,
                                   start_t, end_t, (float*)d_out);
}

// round 8
// speedup vs baseline: 1.5135x; 1.5135x over previous
#include <cuda_runtime.h>
#include <cstdint>
#include <math.h>

#define NT     16
#define S_LEN  4096
#define B_SZ   512
#define CHUNK  8
#define NBLK   (B_SZ / 4)

typedef unsigned long long u64;

// Per-row partial results + completion counter (device globals: legal scratch).
__device__ float g_fwd[B_SZ];
__device__ float g_gold[B_SZ];
__device__ unsigned g_done = 0;

// ---- smem address + volatile LDS/STS helpers ----
__device__ __forceinline__ unsigned smem_addr(const void* p) {
    unsigned a;
    asm("{ .reg .u64 t; cvta.to.shared.u64 t, %1; cvt.u32.u64 %0, t; }"
        : "=r"(a) : "l"(p));
    return a;
}
__device__ __forceinline__ void sts32v(unsigned addr, float v) {
    asm volatile("st.volatile.shared.f32 [%0], %1;" :: "r"(addr), "f"(v));
}
// load 16 floats as 8 packed f32x2 (4x 128-bit volatile LDS)
__device__ __forceinline__ void lds_state(unsigned addr, u64* p) {
    asm volatile("ld.volatile.shared.v2.b64 {%0,%1}, [%2];"
                 : "=l"(p[0]), "=l"(p[1]) : "r"(addr));
    asm volatile("ld.volatile.shared.v2.b64 {%0,%1}, [%2];"
                 : "=l"(p[2]), "=l"(p[3]) : "r"(addr + 16));
    asm volatile("ld.volatile.shared.v2.b64 {%0,%1}, [%2];"
                 : "=l"(p[4]), "=l"(p[5]) : "r"(addr + 32));
    asm volatile("ld.volatile.shared.v2.b64 {%0,%1}, [%2];"
                 : "=l"(p[6]), "=l"(p[7]) : "r"(addr + 48));
}

// ---- packed fp32x2 math (Blackwell FFMA2 path) ----
__device__ __forceinline__ u64 mul2(u64 a, u64 b) {
    u64 d; asm("mul.rn.f32x2 %0, %1, %2;" : "=l"(d) : "l"(a), "l"(b)); return d;
}
__device__ __forceinline__ u64 fma2(u64 a, u64 b, u64 c) {
    u64 d; asm("fma.rn.f32x2 %0, %1, %2, %3;" : "=l"(d) : "l"(a), "l"(b), "l"(c)); return d;
}
__device__ __forceinline__ u64 add2(u64 a, u64 b) {
    u64 d; asm("add.rn.f32x2 %0, %1, %2;" : "=l"(d) : "l"(a), "l"(b)); return d;
}
__device__ __forceinline__ u64 pack2(float lo, float hi) {
    u64 d; asm("mov.b64 %0, {%1, %2};" : "=l"(d) : "f"(lo), "f"(hi)); return d;
}
__device__ __forceinline__ void unpack2(u64 v, float& lo, float& hi) {
    asm("mov.b64 {%0, %1}, %2;" : "=f"(lo), "=f"(hi) : "l"(v));
}

// Detect element strides (bytes) of tags/mask buffers (JAX dtype ambiguity).
__device__ __forceinline__ int detect_mask_stride(const unsigned char* mb) {
    return (mb[1] | mb[2] | mb[3]) ? 1 : 4;
}
__device__ __forceinline__ int detect_tag_stride(const void* tp) {
    const int* w = (const int*)tp;
    int nz = 0;
#pragma unroll
    for (int k = 0; k < 32; ++k) nz |= w[1 + 2 * k];   // high halves if int64
    return nz ? 4 : 8;
}

// One forward step for one stream. p[8] = gathered state (packed pairs),
// eT2[8] = packed transition columns. Updates s/ksum, publishes to 'dst'.
__device__ __forceinline__ void fwd_step(const u64* p, const u64* eT2,
                                         float e, int m,
                                         float& s, int& ksum, unsigned dst)
{
    // per-step rescale from state[0]'s exponent (exact 2^-k, off-chain)
    const unsigned ub = (unsigned)p[0];           // low 32 bits = s[0]
    const int ef = (int)((ub >> 23) & 0xffu);
    int   kcur;
    float scale;
    if (ef >= 1 && ef <= 253) {
        kcur  = ef - 127;
        scale = __uint_as_float((unsigned)(254 - ef) << 23);
    } else {
        kcur = 0; scale = 1.0f;
    }

    // 16-term dot as two packed chains of 4
    u64 a = mul2(p[0], eT2[0]);
    a = fma2(p[2], eT2[2], a);
    a = fma2(p[4], eT2[4], a);
    a = fma2(p[6], eT2[6], a);
    u64 b = mul2(p[1], eT2[1]);
    b = fma2(p[3], eT2[3], b);
    b = fma2(p[5], eT2[5], b);
    b = fma2(p[7], eT2[7], b);
    const u64 t2 = add2(a, b);
    float lo, hi;
    unpack2(t2, lo, hi);
    const float acc = lo + hi;

    const float w  = __expf(e) * scale;           // e prefetched: off-chain
    const float ns = acc * w;
    s    = m ? ns : s;
    ksum += m ? kcur : 0;
    sts32v(dst, s);
}

// One block = 64 threads = 2 warps, covering 4 batch rows.
//   warp 0: forward, 2 overlapped streams x 2 rows (16 lanes/row)
//   warp 1: gold path score, loops over the 4 rows (16 lanes/row, 2 at a time)
__global__ void __launch_bounds__(64, 1) crf_fused_kernel(
    const float* __restrict__ emissions,          // [B, S, NT] f32
    const void*  __restrict__ tags_raw,           // [B, S] i32 or i64
    const void*  __restrict__ mask_raw,           // [B, S] u8 or i32 (bool)
    const float* __restrict__ transitions,        // [NT, NT] f32
    const float* __restrict__ start_t,            // [NT] f32
    const float* __restrict__ end_t,              // [NT] f32
    float* __restrict__ out)
{
    const int warp = threadIdx.x >> 5;
    const int lane = threadIdx.x & 31;
    const int j    = lane & 15;                  // tag index
    const int r    = lane >> 4;                  // row-within-stream (0/1)

    const unsigned char* mask_b = (const unsigned char*)mask_raw;
    const unsigned char* tags_b = (const unsigned char*)tags_raw;
    const int mstride = detect_mask_stride(mask_b);

    // state buffers: [stream][parity][rowInStream][tag]  (warp-0 private)
    __shared__ float sbuf[2][2][2][NT];
    __shared__ int   s_last;

    if (warp == 0) {
        // ---------------- forward: 2 streams, rows 4b+{0,1} and 4b+{2,3} ----------
        const int row0 = blockIdx.x * 4 + r;          // stream 0
        const int row1 = row0 + 2;                    // stream 1

        // packed transition column j: eT2[i] = (eT[2i][j], eT[2i+1][j])
        u64 eT2[8];
#pragma unroll
        for (int i = 0; i < 8; ++i)
            eT2[i] = pack2(__expf(transitions[(2 * i) * NT + j]),
                           __expf(transitions[(2 * i + 1) * NT + j]));

        const float* er0 = emissions + (size_t)row0 * S_LEN * NT + j;
        const float* er1 = emissions + (size_t)row1 * S_LEN * NT + j;
        const unsigned char* mr0 = mask_b + (size_t)row0 * S_LEN * mstride;
        const unsigned char* mr1 = mask_b + (size_t)row1 * S_LEN * mstride;

        float s0 = __expf(start_t[j] + er0[0]);
        float s1 = __expf(start_t[j] + er1[0]);
        int   k0 = 0, k1 = 0;

        const unsigned sb = smem_addr(&sbuf[0][0][0][0]);
        // addr(stream st, parity pp, row r) = sb + st*256 + pp*128 + r*64
        const unsigned b0 = sb + (unsigned)(r * 64);          // stream 0 base
        const unsigned b1 = sb + 256u + (unsigned)(r * 64);   // stream 1 base
        const unsigned jb = (unsigned)(j * 4);
        unsigned par = 0;                                      // parity byte offset

        sts32v(b0 + jb, s0);                       // publish init, parity 0
        sts32v(b1 + jb, s1);

        // prefetch pipelines (per stream)
        float e0[CHUNK], e1[CHUNK];
        int   m0[CHUNK], m1[CHUNK];
#pragma unroll
        for (int p = 0; p < CHUNK; ++p) {
            e0[p] = er0[(size_t)p * NT];  m0[p] = mr0[(size_t)p * mstride];
            e1[p] = er1[(size_t)p * NT];  m1[p] = mr1[(size_t)p * mstride];
        }

        for (int tb = 0; tb < S_LEN; tb += CHUNK) {
#pragma unroll
            for (int u = 0; u < CHUNK; ++u) {
                const int t = tb + u;
                const int mm0 = (t == 0) ? 0 : m0[u];
                const int mm1 = (t == 0) ? 0 : m1[u];
                const float ee0 = e0[u], ee1 = e1[u];

                // ---- gathers for BOTH streams first (reads of last iter's stores)
                u64 v0[8], v1[8];
                lds_state(b0 + par, v0);
                lds_state(b1 + par, v1);

                // prefetch t+CHUNK (LDG issue fills LDS latency)
                const int tp = t + CHUNK;
                if (tp < S_LEN) {
                    e0[u] = er0[(size_t)tp * NT];  m0[u] = mr0[(size_t)tp * mstride];
                    e1[u] = er1[(size_t)tp * NT];  m1[u] = mr1[(size_t)tp * mstride];
                }

                const unsigned npar = par ^ 128u;

                // ---- both trees (independent: ILP), stores last
                fwd_step(v0, eT2, ee0, mm0, s0, k0, b0 + npar + jb);
                fwd_step(v1, eT2, ee1, mm1, s1, k1, b1 + npar + jb);

                par = npar;
            }
        }

        // forward scores
        const float et = __expf(end_t[j]);
        float r0s = s0 * et, r1s = s1 * et;
#pragma unroll
        for (int off = 8; off >= 1; off >>= 1) {
            r0s += __shfl_xor_sync(0xffffffffu, r0s, off, 16);
            r1s += __shfl_xor_sync(0xffffffffu, r1s, off, 16);
        }
        if (j == 0) {
            g_fwd[row0] = logf(r0s) + (float)k0 * 0.6931471805599453f;
            g_fwd[row1] = logf(r1s) + (float)k1 * 0.6931471805599453f;
        }
    } else {
        // ---------------- gold path score (fp32 exact), 4 rows ----------------
        const int tstride = detect_tag_stride(tags_raw);
#pragma unroll
        for (int r2 = 0; r2 < 2; ++r2) {
            const int row = blockIdx.x * 4 + r2 * 2 + (lane >> 4);
            const unsigned char* trow = tags_b + (size_t)row * S_LEN * tstride;
            const unsigned char* mrow = mask_b + (size_t)row * S_LEN * mstride;
            const float*         erow = emissions + (size_t)row * S_LEN * NT;

            float acc = 0.0f;
            int   cnt = 0;
            for (int t = j; t < S_LEN; t += 16) {
                const int tg = trow[(size_t)t * tstride];
                const int mm = mrow[(size_t)t * mstride];
                cnt += mm ? 1 : 0;
                if (t == 0) {
                    acc += start_t[tg] + erow[tg];
                } else if (mm) {
                    const int tpv = trow[(size_t)(t - 1) * tstride];
                    acc += transitions[tpv * NT + tg] + erow[(size_t)t * NT + tg];
                }
            }
#pragma unroll
            for (int off = 8; off >= 1; off >>= 1) {
                acc += __shfl_xor_sync(0xffffffffu, acc, off, 16);
                cnt += __shfl_xor_sync(0xffffffffu, cnt, off, 16);
            }
            if (j == 0) {
                int last = cnt - 1;
                if (last < 0) last = 0;
                const int lt = trow[(size_t)last * tstride];
                g_gold[row] = acc + end_t[lt];
            }
        }
    }

    // ---------------- last-block reduction ----------------
    __syncthreads();
    if (threadIdx.x == 0) {
        __threadfence();
        const unsigned old = atomicAdd(&g_done, 1u);
        s_last = (old == NBLK - 1u) ? 1 : 0;
    }
    __syncthreads();
    if (s_last) {
        __threadfence();
        float a = 0.0f;
        for (int i = threadIdx.x; i < B_SZ; i += 64)
            a += g_fwd[i] - g_gold[i];
#pragma unroll
        for (int off = 16; off >= 1; off >>= 1)
            a += __shfl_xor_sync(0xffffffffu, a, off);
        __shared__ float wsum[2];
        if ((threadIdx.x & 31) == 0) wsum[threadIdx.x >> 5] = a;
        __syncthreads();
        if (threadIdx.x == 0) {
            out[0] = (wsum[0] + wsum[1]) * (1.0f / (float)B_SZ);
            g_done = 0;                      // reset for next graph replay
        }
    }
}

extern "C" void kernel_launch(void* const* d_in, const int* in_sizes, int n_in,
                              void* d_out, int out_size)
{
    (void)in_sizes; (void)n_in; (void)out_size;
    const float* emissions   = (const float*)d_in[0];
    const void*  tags        = d_in[1];
    const void*  mask        = d_in[2];
    const float* transitions = (const float*)d_in[3];
    const float* start_t     = (const float*)d_in[4];
    const float* end_t       = (const float*)d_in[5];

    crf_fused_kernel<<<NBLK, 64>>>(emissions, tags, mask, transitions,
                                   start_t, end_t, (float*)d_out);
}

// round 9
// speedup vs baseline: 2.9445x; 1.9454x over previous
#include <cuda_runtime.h>
#include <cstdint>
#include <math.h>

#define NT     16
#define S_LEN  4096
#define B_SZ   512
#define CHUNK  8
#define NBLK   (B_SZ / 2)

typedef unsigned long long u64;

// Per-row partial results + completion counter (device globals: legal scratch).
__device__ float g_fwd[B_SZ];
__device__ float g_gold[B_SZ];
__device__ unsigned g_done = 0;

// ---- smem helpers: plain LDS/STS inside asm volatile (compiler-ordered,
// ptxas-schedulable; same-warp same-address RAW is ordered by the LSU) ----
__device__ __forceinline__ unsigned smem_addr(const void* p) {
    unsigned a;
    asm("{ .reg .u64 t; cvta.to.shared.u64 t, %1; cvt.u32.u64 %0, t; }"
        : "=r"(a) : "l"(p));
    return a;
}
__device__ __forceinline__ void sts32(unsigned addr, float v) {
    asm volatile("st.shared.f32 [%0], %1;" :: "r"(addr), "f"(v));
}
__device__ __forceinline__ void lds4(unsigned a, u64* p) {
    asm volatile("ld.shared.v2.b64 {%0,%1}, [%2];" : "=l"(p[0]), "=l"(p[1]) : "r"(a));
    asm volatile("ld.shared.v2.b64 {%0,%1}, [%2];" : "=l"(p[2]), "=l"(p[3]) : "r"(a + 16));
    asm volatile("ld.shared.v2.b64 {%0,%1}, [%2];" : "=l"(p[4]), "=l"(p[5]) : "r"(a + 32));
    asm volatile("ld.shared.v2.b64 {%0,%1}, [%2];" : "=l"(p[6]), "=l"(p[7]) : "r"(a + 48));
}

// ---- packed fp32x2 math ----
__device__ __forceinline__ u64 mul2(u64 a, u64 b) {
    u64 d; asm("mul.rn.f32x2 %0, %1, %2;" : "=l"(d) : "l"(a), "l"(b)); return d;
}
__device__ __forceinline__ u64 fma2(u64 a, u64 b, u64 c) {
    u64 d; asm("fma.rn.f32x2 %0, %1, %2, %3;" : "=l"(d) : "l"(a), "l"(b), "l"(c)); return d;
}
__device__ __forceinline__ u64 add2(u64 a, u64 b) {
    u64 d; asm("add.rn.f32x2 %0, %1, %2;" : "=l"(d) : "l"(a), "l"(b)); return d;
}
__device__ __forceinline__ u64 pack2(float lo, float hi) {
    u64 d; asm("mov.b64 %0, {%1, %2};" : "=l"(d) : "f"(lo), "f"(hi)); return d;
}
__device__ __forceinline__ void unpack2(u64 v, float& lo, float& hi) {
    asm("mov.b64 {%0, %1}, %2;" : "=f"(lo), "=f"(hi) : "l"(v));
}

// Detect element strides (bytes) of tags/mask buffers (JAX dtype ambiguity).
__device__ __forceinline__ int detect_mask_stride(const unsigned char* mb) {
    return (mb[1] | mb[2] | mb[3]) ? 1 : 4;
}
__device__ __forceinline__ int detect_tag_stride(const void* tp) {
    const int* w = (const int*)tp;
    int nz = 0;
#pragma unroll
    for (int k = 0; k < 32; ++k) nz |= w[1 + 2 * k];   // high halves if int64
    return nz ? 4 : 8;
}

// One block = 64 threads = 2 warps, 2 batch rows (round-6 shape).
//   warp 0: forward (16 lanes/row, smem ping-pong transport)
//   warp 1: gold path score
__global__ void __launch_bounds__(64, 1) crf_fused_kernel(
    const float* __restrict__ emissions,          // [B, S, NT] f32
    const void*  __restrict__ tags_raw,           // [B, S] i32 or i64
    const void*  __restrict__ mask_raw,           // [B, S] u8 or i32 (bool)
    const float* __restrict__ transitions,        // [NT, NT] f32
    const float* __restrict__ start_t,            // [NT] f32
    const float* __restrict__ end_t,              // [NT] f32
    float* __restrict__ out)
{
    const int warp = threadIdx.x >> 5;
    const int lane = threadIdx.x & 31;
    const int j    = lane & 15;                  // tag index
    const int r    = lane >> 4;                  // row-within-warp (0/1)
    const int row  = blockIdx.x * 2 + r;

    const unsigned char* mask_b = (const unsigned char*)mask_raw;
    const unsigned char* tags_b = (const unsigned char*)tags_raw;
    const int mstride = detect_mask_stride(mask_b);

    // ping-pong state: [parity][rowInWarp][tag]  (warp-0 private)
    __shared__ float sbuf[2][2][NT];
    __shared__ int   s_last;

    if (warp == 0) {
        // ---------------- forward (fp32 linear space, exponent-folded rescale) ----
        // packed transition column j: eT2[i] = (eT[2i][j], eT[2i+1][j])
        u64 eT2[8];
#pragma unroll
        for (int i = 0; i < 8; ++i)
            eT2[i] = pack2(__expf(transitions[(2 * i) * NT + j]),
                           __expf(transitions[(2 * i + 1) * NT + j]));

        const float* erow = emissions + (size_t)row * S_LEN * NT + j;
        const unsigned char* mrow = mask_b + (size_t)row * S_LEN * mstride;

        float s = __expf(start_t[j] + erow[0]);
        int   ksum = 0;

        const unsigned sb    = smem_addr(&sbuf[0][0][0]);
        const unsigned rbase = sb + (unsigned)(r * 64);
        const unsigned jb    = (unsigned)(j * 4);
        unsigned par = 0;                         // parity byte offset (0 / 128)

        sts32(rbase + jb, s);                     // publish init (parity 0)

        // register prefetch pipeline
        float ebuf[CHUNK];
        int   mbuf[CHUNK];
#pragma unroll
        for (int p = 0; p < CHUNK; ++p) {
            ebuf[p] = erow[(size_t)p * NT];
            mbuf[p] = mrow[(size_t)p * mstride];
        }

        for (int tb = 0; tb < S_LEN; tb += CHUNK) {
#pragma unroll
            for (int u = 0; u < CHUNK; ++u) {
                const int t = tb + u;
                const int m = (t == 0) ? 0 : mbuf[u];

                // emission weight exp: fully off-chain (e loaded CHUNK steps ago)
                const float wpre = __expf(ebuf[u]);

                // gather state (4x LDS.128 broadcast)
                u64 v[8];
                lds4(rbase + par, v);

                // prefetch t+CHUNK (free to float anywhere)
                const int tp = t + CHUNK;
                if (tp < S_LEN) {
                    ebuf[u] = erow[(size_t)tp * NT];
                    mbuf[u] = mrow[(size_t)tp * mstride];
                }

                // rescale folded into W via exponent arithmetic:
                //   kcur = exp2-exponent of s0;  W = wpre * 2^-kcur
                const unsigned ub  = (unsigned)v[0];          // bits of s0
                const int kcur = (int)((ub >> 23) & 0xffu) - 127;
                const unsigned wb =
                    __float_as_uint(wpre) + 0x3f800000u - (ub & 0x7f800000u);
                const float W = __uint_as_float(wb);

                // balanced packed tree: depth ~24, 13 instrs
                u64 p0 = mul2(v[0], eT2[0]);
                u64 p1 = mul2(v[1], eT2[1]);
                u64 p2 = mul2(v[2], eT2[2]);
                u64 p3 = mul2(v[3], eT2[3]);
                p0 = fma2(v[4], eT2[4], p0);
                p1 = fma2(v[5], eT2[5], p1);
                p2 = fma2(v[6], eT2[6], p2);
                p3 = fma2(v[7], eT2[7], p3);
                const u64 q0 = add2(p0, p1);
                const u64 q1 = add2(p2, p3);
                const u64 qq = add2(q0, q1);
                float lo, hi;
                unpack2(qq, lo, hi);
                const float acc = lo + hi;

                const float ns = acc * W;
                s    = m ? ns : s;
                ksum += m * kcur;

                // publish to other parity; compiler keeps order, LSU keeps RAW
                par ^= 128u;
                sts32(rbase + par + jb, s);
            }
        }

        float rsum = s * __expf(end_t[j]);
#pragma unroll
        for (int off = 8; off >= 1; off >>= 1)
            rsum += __shfl_xor_sync(0xffffffffu, rsum, off, 16);
        if (j == 0)
            g_fwd[row] = logf(rsum) + (float)ksum * 0.6931471805599453f;
    } else {
        // ---------------- gold path score (fp32 exact) ----------------
        const int tstride = detect_tag_stride(tags_raw);
        const unsigned char* trow = tags_b + (size_t)row * S_LEN * tstride;
        const unsigned char* mrow = mask_b + (size_t)row * S_LEN * mstride;
        const float*         erow = emissions + (size_t)row * S_LEN * NT;

        float acc = 0.0f;
        int   cnt = 0;
        for (int t = j; t < S_LEN; t += 16) {
            const int tg = trow[(size_t)t * tstride];
            const int mm = mrow[(size_t)t * mstride];
            cnt += mm ? 1 : 0;
            if (t == 0) {
                acc += start_t[tg] + erow[tg];
            } else if (mm) {
                const int tpv = trow[(size_t)(t - 1) * tstride];
                acc += transitions[tpv * NT + tg] + erow[(size_t)t * NT + tg];
            }
        }
#pragma unroll
        for (int off = 8; off >= 1; off >>= 1) {
            acc += __shfl_xor_sync(0xffffffffu, acc, off, 16);
            cnt += __shfl_xor_sync(0xffffffffu, cnt, off, 16);
        }
        if (j == 0) {
            int last = cnt - 1;
            if (last < 0) last = 0;
            const int lt = trow[(size_t)last * tstride];
            g_gold[row] = acc + end_t[lt];
        }
    }

    // ---------------- last-block reduction ----------------
    __syncthreads();
    if (threadIdx.x == 0) {
        __threadfence();
        const unsigned old = atomicAdd(&g_done, 1u);
        s_last = (old == NBLK - 1u) ? 1 : 0;
    }
    __syncthreads();
    if (s_last) {
        __threadfence();
        float a = 0.0f;
        for (int i = threadIdx.x; i < B_SZ; i += 64)
            a += g_fwd[i] - g_gold[i];
#pragma unroll
        for (int off = 16; off >= 1; off >>= 1)
            a += __shfl_xor_sync(0xffffffffu, a, off);
        __shared__ float wsum[2];
        if ((threadIdx.x & 31) == 0) wsum[threadIdx.x >> 5] = a;
        __syncthreads();
        if (threadIdx.x == 0) {
            out[0] = (wsum[0] + wsum[1]) * (1.0f / (float)B_SZ);
            g_done = 0;                      // reset for next graph replay
        }
    }
}

extern "C" void kernel_launch(void* const* d_in, const int* in_sizes, int n_in,
                              void* d_out, int out_size)
{
    (void)in_sizes; (void)n_in; (void)out_size;
    const float* emissions   = (const float*)d_in[0];
    const void*  tags        = d_in[1];
    const void*  mask        = d_in[2];
    const float* transitions = (const float*)d_in[3];
    const float* start_t     = (const float*)d_in[4];
    const float* end_t       = (const float*)d_in[5];

    crf_fused_kernel<<<NBLK, 64>>>(emissions, tags, mask, transitions,
                                   start_t, end_t, (float*)d_out);
}